// round 16
// baseline (speedup 1.0000x reference)
#include <cuda_runtime.h>
#include <cstdint>

// PatchEmbedder: B=8, P=1024, D=512, BUCKETS=65536, LS=(8,7,6)
//
// R13 shape (measured 23.04us, reproducible) + interleaved dual gather:
//   - Inputs identified by element count (host side):
//       33554432 -> emb tables (3, appearance order), 8192 -> patch_mask,
//       65536/57344/49152 -> {ids_k, mask_k} pairs.
//   - Layout (ids-vs-mask per pair, mask width u8/i32/f32, patch_mask width,
//     ids stride i32/i64) detected by ONE tiny probe launch (7 warps).
//   - Main kernel: 2 patches per CTA, staged concurrently by two disjoint
//     thread groups, one __syncthreads, then ONE interleaved gather loop
//     issuing patch-A and patch-B row loads as pairs (two independent load
//     chains per thread -> no pipeline drain between patches).
//   - Conditional __ldg float4 gathers (masked rows skipped), __stcs output.
//
// Floor: ~86MB compulsory DRAM traffic at the measured random-2KB-row
// ceiling (~3.5TB/s) => ~25us kernel + overhead.

#define NPATCH (8 * 1024)
#define DV 128          // 512 floats = 128 float4 per embedding row
#define L1N 8
#define L2N 7
#define L3N 6
#define LTOT (L1N + L2N + L3N)  // 21

// g_cfg: [0..2] swap_k  [3..5] ids stride (1|2)  [6..8] mask width (1|4)
//        [9] patch_mask width (1|4)
__device__ int g_cfg[10];

// 7 warps: warp c probes buffer c (0..5 = a1,b1,a2,b2,a3,b3; 6 = patch_mask).
__global__ void probe_kernel(const unsigned char* a1, const unsigned char* b1,
                             const unsigned char* a2, const unsigned char* b2,
                             const unsigned char* a3, const unsigned char* b3,
                             const unsigned char* pm)
{
    const int w = threadIdx.x >> 5;      // 0..6
    const int lane = threadIdx.x & 31;
    const unsigned char* cand[7] = {a1, b1, a2, b2, a3, b3, pm};
    const int nbytes[7] = {65536, 65536, 57344, 57344, 49152, 49152, 8192};

    __shared__ int s_isMask[7], s_odd[7], s_wide[7];

    {
        const unsigned char* p = cand[w];
        const int n = nbytes[w];
        const unsigned char bv = p[(size_t)lane * (size_t)(n / 32)];
        const unsigned wv = ((const unsigned*)p)[(size_t)lane * (size_t)((n / 4) / 32)];
        const int      ov = ((const int*)p)[2 * lane + 1];

        unsigned v = 0;
        if (bv > 1)                        v |= 1;   // byte-bool violated
        if (wv > 1u)                       v |= 2;   // word-int-bool violated
        if (wv != 0u && wv != 0x3F800000u) v |= 4;   // word-float-bool violated
        if (ov != 0)                       v |= 8;   // odd-words-zero violated
        v = __reduce_or_sync(0xFFFFFFFFu, v);

        if (lane == 0) {
            s_isMask[w] = (!(v & 2)) || (!(v & 4)) || (!(v & 1));
            s_odd[w]    = (v & 8) ? 1 : 0;
            s_wide[w]   = ((!(v & 2)) || (!(v & 4))) ? 1 : 0;   // 4-byte bool
        }
    }
    __syncthreads();

    if (threadIdx.x == 0) {
        for (int k = 0; k < 3; k++) {
            const int A = 2 * k, B = 2 * k + 1;
            const int swap = (s_isMask[A] && !s_isMask[B]) ? 1 : 0;
            const int idsI = swap ? B : A;
            const int mI   = swap ? A : B;
            g_cfg[k]     = swap;
            g_cfg[3 + k] = s_odd[idsI] ? 1 : 2;   // odd words all zero => int64
            g_cfg[6 + k] = s_wide[mI] ? 4 : 1;
        }
        g_cfg[9] = s_wide[6] ? 4 : 1;
    }
}

__device__ __forceinline__ int read_mask(const unsigned char* m, int idx, int w) {
    return (w == 4) ? (((const int*)m)[idx] != 0) : (m[idx] != 0);
}

// Stage slot `slot` (0..20) of `patch`: returns row pointer or nullptr.
__device__ __forceinline__ const float4* stage_slot(
    int patch, int slot,
    const unsigned char* a1, const unsigned char* b1,
    const unsigned char* a2, const unsigned char* b2,
    const unsigned char* a3, const unsigned char* b3,
    const unsigned char* pmask,
    const float4* e1, const float4* e2, const float4* e3)
{
    if (!read_mask(pmask, patch, g_cfg[9])) return nullptr;
    int k, j, nk;
    const unsigned char *pa, *pb;
    const float4* e;
    if (slot < L1N)            { k = 0; j = slot;             nk = L1N; pa = a1; pb = b1; e = e1; }
    else if (slot < L1N + L2N) { k = 1; j = slot - L1N;       nk = L2N; pa = a2; pb = b2; e = e2; }
    else                       { k = 2; j = slot - L1N - L2N; nk = L3N; pa = a3; pb = b3; e = e3; }

    const int swap = g_cfg[k];
    const int st   = g_cfg[3 + k];
    const int wm   = g_cfg[6 + k];
    const unsigned char* ids = swap ? pb : pa;
    const unsigned char* msk = swap ? pa : pb;
    const int idx = patch * nk + j;
    if (!read_mask(msk, idx, wm)) return nullptr;
    const unsigned id = (unsigned)((const int*)ids)[idx * st] & 0xFFFFu;
    return e + (size_t)id * DV;
}

__global__ __launch_bounds__(128, 16) void patch_embed_kernel(
    const unsigned char* __restrict__ a1, const unsigned char* __restrict__ b1,
    const unsigned char* __restrict__ a2, const unsigned char* __restrict__ b2,
    const unsigned char* __restrict__ a3, const unsigned char* __restrict__ b3,
    const unsigned char* __restrict__ pmask,
    const float4* __restrict__ e1,
    const float4* __restrict__ e2,
    const float4* __restrict__ e3,
    float4* __restrict__ out)
{
    __shared__ const float4* ptrs[2][LTOT];

    const int pA = blockIdx.x * 2;       // 0..8190 (even)
    const int pB = pA + 1;
    const int t = threadIdx.x;           // 0..127

    // ---- concurrent staging: t<21 stages patch A, 64<=t<85 stages patch B ----
    if (t < LTOT)
        ptrs[0][t] = stage_slot(pA, t, a1, b1, a2, b2, a3, b3, pmask, e1, e2, e3);
    else if (t >= 64 && t < 64 + LTOT)
        ptrs[1][t - 64] = stage_slot(pB, t - 64, a1, b1, a2, b2, a3, b3, pmask, e1, e2, e3);
    __syncthreads();

    // ---- interleaved gather: A_i and B_i issued as a pair each iteration ----
    float4 accA = make_float4(0.f, 0.f, 0.f, 0.f);
    float4 accB = make_float4(0.f, 0.f, 0.f, 0.f);
#pragma unroll
    for (int i = 0; i < LTOT; i++) {
        const float4* qA = ptrs[0][i];   // warp-uniform branches
        const float4* qB = ptrs[1][i];
        if (qA) {
            const float4 v = __ldg(qA + t);
            accA.x += v.x; accA.y += v.y; accA.z += v.z; accA.w += v.w;
        }
        if (qB) {
            const float4 v = __ldg(qB + t);
            accB.x += v.x; accB.y += v.y; accB.z += v.z; accB.w += v.w;
        }
    }

    // Evict-first stores: dead output must not displace rows in L2.
    __stcs(&out[(size_t)pA * DV + t], accA);
    __stcs(&out[(size_t)pB * DV + t], accB);
}

extern "C" void kernel_launch(void* const* d_in, const int* in_sizes, int n_in,
                              void* d_out, int out_size)
{
    const unsigned char *a1 = nullptr, *b1 = nullptr;
    const unsigned char *a2 = nullptr, *b2 = nullptr;
    const unsigned char *a3 = nullptr, *b3 = nullptr;
    const unsigned char *pm = nullptr;
    const float4* emb[3] = {nullptr, nullptr, nullptr};
    int ne = 0;

    for (int i = 0; i < n_in; i++) {
        const int sz = in_sizes[i];
        const unsigned char* p = (const unsigned char*)d_in[i];
        switch (sz) {
            case 33554432: if (ne < 3) emb[ne++] = (const float4*)p; break;
            case 8192:     pm = p; break;
            case 65536:    if (!a1) a1 = p; else b1 = p; break;
            case 57344:    if (!a2) a2 = p; else b2 = p; break;
            case 49152:    if (!a3) a3 = p; else b3 = p; break;
            default: break;
        }
    }

    probe_kernel<<<1, 224>>>(a1, b1, a2, b2, a3, b3, pm);
    patch_embed_kernel<<<NPATCH / 2, 128>>>(a1, b1, a2, b2, a3, b3, pm,
                                            emb[0], emb[1], emb[2],
                                            (float4*)d_out);
}

// round 17
// speedup vs baseline: 1.0976x; 1.0976x over previous
#include <cuda_runtime.h>
#include <cstdint>

// PatchEmbedder: B=8, P=1024, D=512, BUCKETS=65536, LS=(8,7,6)
//
// Variant of the 23.04us plateau kernel: 256-thread CTAs, 2 patches per CTA
// gathered IN PARALLEL by disjoint thread halves (t<128 -> patch A,
// t>=128 -> patch B); staging concurrent (warp 0 stages A, warp 4 stages B),
// one __syncthreads. Conditional __ldg float4 gathers (masked rows skipped),
// __stcs evict-first output stores.
//
//   - Inputs identified by element count (host side):
//       33554432 -> emb tables (3, appearance order), 8192 -> patch_mask,
//       65536/57344/49152 -> {ids_k, mask_k} pairs.
//   - Layout (ids-vs-mask per pair, mask width u8/i32/f32, patch_mask width,
//     ids stride i32/i64) detected by ONE tiny probe launch (7 warps).
//
// Floor model: ~86MB compulsory DRAM traffic at the measured random-2KB-row
// ceiling (~3.4TB/s) => ~25us kernel + overhead; 23.04us total measured
// repeatedly across three code shapes.

#define NPATCH (8 * 1024)
#define DV 128          // 512 floats = 128 float4 per embedding row
#define L1N 8
#define L2N 7
#define L3N 6
#define LTOT (L1N + L2N + L3N)  // 21

// g_cfg: [0..2] swap_k  [3..5] ids stride (1|2)  [6..8] mask width (1|4)
//        [9] patch_mask width (1|4)
__device__ int g_cfg[10];

// 7 warps: warp c probes buffer c (0..5 = a1,b1,a2,b2,a3,b3; 6 = patch_mask).
__global__ void probe_kernel(const unsigned char* a1, const unsigned char* b1,
                             const unsigned char* a2, const unsigned char* b2,
                             const unsigned char* a3, const unsigned char* b3,
                             const unsigned char* pm)
{
    const int w = threadIdx.x >> 5;      // 0..6
    const int lane = threadIdx.x & 31;
    const unsigned char* cand[7] = {a1, b1, a2, b2, a3, b3, pm};
    const int nbytes[7] = {65536, 65536, 57344, 57344, 49152, 49152, 8192};

    __shared__ int s_isMask[7], s_odd[7], s_wide[7];

    {
        const unsigned char* p = cand[w];
        const int n = nbytes[w];
        const unsigned char bv = p[(size_t)lane * (size_t)(n / 32)];
        const unsigned wv = ((const unsigned*)p)[(size_t)lane * (size_t)((n / 4) / 32)];
        const int      ov = ((const int*)p)[2 * lane + 1];

        unsigned v = 0;
        if (bv > 1)                        v |= 1;   // byte-bool violated
        if (wv > 1u)                       v |= 2;   // word-int-bool violated
        if (wv != 0u && wv != 0x3F800000u) v |= 4;   // word-float-bool violated
        if (ov != 0)                       v |= 8;   // odd-words-zero violated
        v = __reduce_or_sync(0xFFFFFFFFu, v);

        if (lane == 0) {
            s_isMask[w] = (!(v & 2)) || (!(v & 4)) || (!(v & 1));
            s_odd[w]    = (v & 8) ? 1 : 0;
            s_wide[w]   = ((!(v & 2)) || (!(v & 4))) ? 1 : 0;   // 4-byte bool
        }
    }
    __syncthreads();

    if (threadIdx.x == 0) {
        for (int k = 0; k < 3; k++) {
            const int A = 2 * k, B = 2 * k + 1;
            const int swap = (s_isMask[A] && !s_isMask[B]) ? 1 : 0;
            const int idsI = swap ? B : A;
            const int mI   = swap ? A : B;
            g_cfg[k]     = swap;
            g_cfg[3 + k] = s_odd[idsI] ? 1 : 2;   // odd words all zero => int64
            g_cfg[6 + k] = s_wide[mI] ? 4 : 1;
        }
        g_cfg[9] = s_wide[6] ? 4 : 1;
    }
}

__device__ __forceinline__ int read_mask(const unsigned char* m, int idx, int w) {
    return (w == 4) ? (((const int*)m)[idx] != 0) : (m[idx] != 0);
}

// Stage slot `slot` (0..20) of `patch`: returns row pointer or nullptr.
__device__ __forceinline__ const float4* stage_slot(
    int patch, int slot,
    const unsigned char* a1, const unsigned char* b1,
    const unsigned char* a2, const unsigned char* b2,
    const unsigned char* a3, const unsigned char* b3,
    const unsigned char* pmask,
    const float4* e1, const float4* e2, const float4* e3)
{
    if (!read_mask(pmask, patch, g_cfg[9])) return nullptr;
    int k, j, nk;
    const unsigned char *pa, *pb;
    const float4* e;
    if (slot < L1N)            { k = 0; j = slot;             nk = L1N; pa = a1; pb = b1; e = e1; }
    else if (slot < L1N + L2N) { k = 1; j = slot - L1N;       nk = L2N; pa = a2; pb = b2; e = e2; }
    else                       { k = 2; j = slot - L1N - L2N; nk = L3N; pa = a3; pb = b3; e = e3; }

    const int swap = g_cfg[k];
    const int st   = g_cfg[3 + k];
    const int wm   = g_cfg[6 + k];
    const unsigned char* ids = swap ? pb : pa;
    const unsigned char* msk = swap ? pa : pb;
    const int idx = patch * nk + j;
    if (!read_mask(msk, idx, wm)) return nullptr;
    const unsigned id = (unsigned)((const int*)ids)[idx * st] & 0xFFFFu;
    return e + (size_t)id * DV;
}

__global__ __launch_bounds__(256, 8) void patch_embed_kernel(
    const unsigned char* __restrict__ a1, const unsigned char* __restrict__ b1,
    const unsigned char* __restrict__ a2, const unsigned char* __restrict__ b2,
    const unsigned char* __restrict__ a3, const unsigned char* __restrict__ b3,
    const unsigned char* __restrict__ pmask,
    const float4* __restrict__ e1,
    const float4* __restrict__ e2,
    const float4* __restrict__ e3,
    float4* __restrict__ out)
{
    __shared__ const float4* ptrs[2][LTOT];

    const int pA = blockIdx.x * 2;       // 0..8190 (even)
    const int t = threadIdx.x;           // 0..255
    const int half = t >> 7;             // 0 -> patch A, 1 -> patch B
    const int ht = t & 127;              // lane within half
    const int patch = pA + half;

    // ---- concurrent staging: warp 0 stages A, warp 4 stages B ----
    {
        const int w = t >> 5;
        const int lane = t & 31;
        if ((w == 0 || w == 4) && lane < LTOT)
            ptrs[w >> 2][lane] = stage_slot(pA + (w >> 2), lane,
                                            a1, b1, a2, b2, a3, b3,
                                            pmask, e1, e2, e3);
    }
    __syncthreads();

    // ---- gather + sum: each 128-thread half handles its own patch ----
    float4 acc = make_float4(0.f, 0.f, 0.f, 0.f);
#pragma unroll
    for (int i = 0; i < LTOT; i++) {
        const float4* p = ptrs[half][i];     // warp-uniform branch
        if (p) {
            const float4 v = __ldg(p + ht);
            acc.x += v.x; acc.y += v.y; acc.z += v.z; acc.w += v.w;
        }
    }
    // Evict-first store: dead output must not displace rows in L2.
    __stcs(&out[(size_t)patch * DV + ht], acc);
}

extern "C" void kernel_launch(void* const* d_in, const int* in_sizes, int n_in,
                              void* d_out, int out_size)
{
    const unsigned char *a1 = nullptr, *b1 = nullptr;
    const unsigned char *a2 = nullptr, *b2 = nullptr;
    const unsigned char *a3 = nullptr, *b3 = nullptr;
    const unsigned char *pm = nullptr;
    const float4* emb[3] = {nullptr, nullptr, nullptr};
    int ne = 0;

    for (int i = 0; i < n_in; i++) {
        const int sz = in_sizes[i];
        const unsigned char* p = (const unsigned char*)d_in[i];
        switch (sz) {
            case 33554432: if (ne < 3) emb[ne++] = (const float4*)p; break;
            case 8192:     pm = p; break;
            case 65536:    if (!a1) a1 = p; else b1 = p; break;
            case 57344:    if (!a2) a2 = p; else b2 = p; break;
            case 49152:    if (!a3) a3 = p; else b3 = p; break;
            default: break;
        }
    }

    probe_kernel<<<1, 224>>>(a1, b1, a2, b2, a3, b3, pm);
    patch_embed_kernel<<<NPATCH / 2, 256>>>(a1, b1, a2, b2, a3, b3, pm,
                                            emb[0], emb[1], emb[2],
                                            (float4*)d_out);
}